// round 8
// baseline (speedup 1.0000x reference)
#include <cuda_runtime.h>
#include <cstdint>

// Padded binary volume: reference pads 160 -> 162; we add one more guard ring
// (always zero) so every 3x3x3 window at evaluated voxels is in-bounds.
// buffer coord b = padded coord p + 1 = image coord ix + 2.
#define PN    164
#define PN2   (PN*PN)
#define VOLN  (PN*PN*PN)          // 4,410,944

__device__ __align__(16) unsigned char g_vol[2*VOLN];
__device__ unsigned char g_end[2*VOLN];

// ---------------- threefry2x32 (JAX), partitionable 32-bit combine ----------
__device__ __forceinline__ uint32_t rotl32(uint32_t x, int d){ return (x<<d)|(x>>(32-d)); }

__device__ __forceinline__ uint32_t threefry_bits(uint32_t x0, uint32_t x1){
  const uint32_t k0 = 0u, k1 = 42u;
  const uint32_t k2 = k0 ^ k1 ^ 0x1BD11BDAu;
  x0 += k0; x1 += k1;
#define TF_R(r) { x0 += x1; x1 = rotl32(x1,(r)); x1 ^= x0; }
  TF_R(13) TF_R(15) TF_R(26) TF_R(6)
  x0 += k1; x1 += k2 + 1u;
  TF_R(17) TF_R(29) TF_R(16) TF_R(24)
  x0 += k2; x1 += k0 + 2u;
  TF_R(13) TF_R(15) TF_R(26) TF_R(6)
  x0 += k0; x1 += k1 + 3u;
  TF_R(17) TF_R(29) TF_R(16) TF_R(24)
  x0 += k1; x1 += k2 + 4u;
  TF_R(13) TF_R(15) TF_R(26) TF_R(6)
  x0 += k2; x1 += k0 + 5u;
#undef TF_R
  return x0 ^ x1;   // _threefry_random_bits_partitionable: bits1 ^ bits2 for 32-bit
}

// ---------------- kernels ---------------------------------------------------
__global__ void k_zero(){
  int i = blockIdx.x*blockDim.x + threadIdx.x;
  uint4* p = reinterpret_cast<uint4*>(g_vol);
  if (i < (2*VOLN)/16) p[i] = make_uint4(0u,0u,0u,0u);
}

// Gumbel-sigmoid hard binarization, bit-faithful to the JAX reference.
__global__ __launch_bounds__(162) void k_binarize(const float* __restrict__ img){
  int pz = threadIdx.x;              // 0..161 (padded coords)
  int py = blockIdx.x;               // 0..161
  int px = blockIdx.y;               // 0..161
  int n  = blockIdx.z;               // 0..1
  uint32_t lin = ((uint32_t)(((n*162 + px)*162) + py))*162u + (uint32_t)pz;
  uint32_t bits = threefry_bits(0u, lin);

  const float minv  = (float)1e-8;            // 1.0000000117e-8f
  const float maxv  = (float)(1.0 - 1e-8);    // rounds to 1.0f
  const float range = maxv - minv;            // 1.0f

  float fl = __uint_as_float((bits >> 9) | 0x3f800000u) - 1.0f;   // [0,1)
  float u  = fmaxf(minv, __fadd_rn(__fmul_rn(fl, range), minv));
  float noise = __fsub_rn(logf(u), log1pf(-u));                   // logit(u)

  float p = 0.0f;
  if (px>=1 && px<=160 && py>=1 && py<=160 && pz>=1 && pz<=160)
    p = img[ (((n*160) + (px-1))*160 + (py-1))*160 + (pz-1) ];

  float a = __fadd_rn(p, 1e-8f);
  float b = __fadd_rn(__fsub_rn(1.0f, p), 1e-8f);
  float z = __fadd_rn(logf(__fdiv_rn(a, b)), __fmul_rn(noise, 0.33f)); // TAU=1
  float soft = __fdiv_rn(1.0f, __fadd_rn(1.0f, expf(-z)));        // XLA logistic expansion
  unsigned char hard = (soft > 0.5f) ? (unsigned char)1 : (unsigned char)0;

  g_vol[ n*VOLN + ((px+1)*PN + (py+1))*PN + (pz+1) ] = hard;
}

// is_end snapshot: endpoint iff 26-neighborhood sum <= 1. Only needed (and
// only read) at voxels that are 1 at iteration start.
__global__ __launch_bounds__(160) void k_endpoint(){
  int bz = threadIdx.x + 2;          // interior b in [2,162)
  int by = blockIdx.x + 2;
  int bx = blockIdx.y + 2;
  int n  = blockIdx.z;
  const unsigned char* __restrict__ V = g_vol + n*VOLN;
  int c = (bx*PN + by)*PN + bz;
  if (!V[c]) return;                 // value never read while voxel is 0
  int s = 0;
  #pragma unroll
  for (int dx=-1; dx<=1; dx++)
    #pragma unroll
    for (int dy=-1; dy<=1; dy++){
      int r = c + dx*PN2 + dy*PN;
      s += (int)V[r-1] + (int)V[r] + (int)V[r+1];
    }
  s -= 1;                            // remove center (known 1)
  g_end[n*VOLN + c] = (s <= 1) ? (unsigned char)1 : (unsigned char)0;
}

// One parity-subfield simple-point deletion pass. Same-parity 3^3 windows are
// disjoint -> in-place update matches JAX's snapshot semantics.
__global__ __launch_bounds__(320) void k_subfield(int bx0, int by0, int bz0){
  int iz = threadIdx.x;                        // 0..79
  int iy = blockIdx.x*4 + threadIdx.y;         // 0..79
  int ix = blockIdx.y;                         // 0..79
  int n  = blockIdx.z;
  int bx = bx0 + 2*ix, by = by0 + 2*iy, bz = bz0 + 2*iz;
  unsigned char* V = g_vol + n*VOLN;
  int c = (bx*PN + by)*PN + bz;
  if (!V[c]) return;

  int v[27];
  #pragma unroll
  for (int dx=0; dx<3; dx++)
    #pragma unroll
    for (int dy=0; dy<3; dy++){
      int r = c + (dx-1)*PN2 + (dy-1)*PN;
      v[(dx*3+dy)*3+0] = V[r-1];
      v[(dx*3+dy)*3+1] = V[r];
      v[(dx*3+dy)*3+2] = V[r+1];
    }
#define VV(a,b,cc) v[((a)*3+(b))*3+(cc)]
  int fxm=VV(0,1,1), fxp=VV(2,1,1), fym=VV(1,0,1), fyp=VV(1,2,1), fzm=VV(1,1,0), fzp=VV(1,1,2);
  int faceSum = fxm+fxp+fym+fyp+fzm+fzp;
  int n6z = 6 - faceSum;                // # zero face-neighbors (channel 1-p conv)
  int tot = 0;
  #pragma unroll
  for (int i=0;i<27;i++) tot += v[i];
  tot -= VV(1,1,1);
  int corners = VV(0,0,0)+VV(0,0,2)+VV(0,2,0)+VV(0,2,2)
              + VV(2,0,0)+VV(2,0,2)+VV(2,2,0)+VV(2,2,2);
  int n26 = tot;
  int n18 = tot - corners;

  // b26: corner=1 with its 6 same-octant face/edge neighbors all 0 (8 flips)
  int anyB = 0;
  #pragma unroll
  for (int sx=0; sx<=2; sx+=2)
    #pragma unroll
    for (int sy=0; sy<=2; sy+=2)
      #pragma unroll
      for (int sz=0; sz<=2; sz+=2)
        anyB |= VV(sx,sy,sz) &
                (~(VV(sx,sy,1)|VV(sx,1,sz)|VV(sx,1,1)|VV(1,sy,sz)|VV(1,sy,1)|VV(1,1,sz)) & 1);

  // a6: face=0 with its 4 in-plane edge-neighbors all 1 (6 rotations/flips)
  int anyA =
    ((fxm^1) & VV(0,0,1) & VV(0,2,1) & VV(0,1,0) & VV(0,1,2)) |
    ((fxp^1) & VV(2,0,1) & VV(2,2,1) & VV(2,1,0) & VV(2,1,2)) |
    ((fym^1) & VV(0,0,1) & VV(2,0,1) & VV(1,0,0) & VV(1,0,2)) |
    ((fyp^1) & VV(0,2,1) & VV(2,2,1) & VV(1,2,0) & VV(1,2,2)) |
    ((fzm^1) & VV(0,1,0) & VV(2,1,0) & VV(1,0,0) & VV(1,2,0)) |
    ((fzp^1) & VV(0,1,2) & VV(2,1,2) & VV(1,0,2) & VV(1,2,2));

  int simple = (int)(n6z==1) | (int)(n26==1)
             | ((int)(n18==1) & (anyB^1))
             | ((int)(n6z>=2) & (anyA?0:1) & (anyB?0:1));
  if (simple && !g_end[n*VOLN + c]) V[c] = 0;
#undef VV
}

__global__ __launch_bounds__(160) void k_output(float* __restrict__ out){
  int z = threadIdx.x, y = blockIdx.x, x = blockIdx.y, n = blockIdx.z; // 160 each
  out[ ((n*160 + x)*160 + y)*160 + z ] =
      (float)g_vol[ n*VOLN + ((x+2)*PN + (y+2))*PN + (z+2) ];
}

// ---------------- launch -----------------------------------------------------
extern "C" void kernel_launch(void* const* d_in, const int* in_sizes, int n_in,
                              void* d_out, int out_size){
  (void)in_sizes; (void)n_in; (void)out_size;
  const float* img = (const float*)d_in[0];
  float* out = (float*)d_out;

  k_zero<<<((2*VOLN)/16 + 255)/256, 256>>>();
  k_binarize<<<dim3(162,162,2), 162>>>(img);

  const int off[8][3] = {{0,0,0},{1,0,0},{0,1,0},{1,1,0},
                         {0,0,1},{1,0,1},{0,1,1},{1,1,1}};
  for (int it=0; it<5; it++){
    k_endpoint<<<dim3(160,160,2), 160>>>();
    for (int s=0; s<8; s++){
      // parity xo -> interior buffer coords start at 3-xo, 80 steps of 2
      int bx0 = 3 - off[s][0];
      int by0 = 3 - off[s][1];
      int bz0 = 3 - off[s][2];
      k_subfield<<<dim3(20,80,2), dim3(80,4,1)>>>(bx0, by0, bz0);
    }
  }
  k_output<<<dim3(160,160,2), 160>>>(out);
}

// round 9
// speedup vs baseline: 2.1722x; 2.1722x over previous
#include <cuda_runtime.h>
#include <cstdint>

// Bit-packed binary volume: z packed 32 voxels/uint32.
// Row = (n, bx, by), bx,by in [0,164) (guard ring + padded 162), 6 words/row.
// bit index bz = padded z + 1;  buffer coord b = padded p + 1 = image ix + 2.
#define NR    164
#define ROWW  6
#define NROWW (NR*NR*ROWW)        // words per batch item: 161,376
#define NWORDS (2*NROWW)          // 322,752 words = 1.29 MB

__device__ __align__(16) uint32_t g_bits[NWORDS];
__device__ __align__(16) uint32_t g_endb[NWORDS];   // "n26sum >= 2" mask

// ---------------- threefry2x32 (JAX), partitionable 32-bit combine ----------
__device__ __forceinline__ uint32_t rotl32(uint32_t x, int d){ return (x<<d)|(x>>(32-d)); }

__device__ __forceinline__ uint32_t threefry_bits(uint32_t x0, uint32_t x1){
  const uint32_t k0 = 0u, k1 = 42u;
  const uint32_t k2 = k0 ^ k1 ^ 0x1BD11BDAu;
  x0 += k0; x1 += k1;
#define TF_R(r) { x0 += x1; x1 = rotl32(x1,(r)); x1 ^= x0; }
  TF_R(13) TF_R(15) TF_R(26) TF_R(6)
  x0 += k1; x1 += k2 + 1u;
  TF_R(17) TF_R(29) TF_R(16) TF_R(24)
  x0 += k2; x1 += k0 + 2u;
  TF_R(13) TF_R(15) TF_R(26) TF_R(6)
  x0 += k0; x1 += k1 + 3u;
  TF_R(17) TF_R(29) TF_R(16) TF_R(24)
  x0 += k1; x1 += k2 + 4u;
  TF_R(13) TF_R(15) TF_R(26) TF_R(6)
  x0 += k2; x1 += k0 + 5u;
#undef TF_R
  return x0 ^ x1;
}

// ---------------- kernels ---------------------------------------------------
__global__ void k_zero(){
  int i = blockIdx.x*blockDim.x + threadIdx.x;
  if (i < NWORDS/4) reinterpret_cast<uint4*>(g_bits)[i] = make_uint4(0u,0u,0u,0u);
}

// Gumbel-sigmoid hard binarization (bit-exact vs passing scalar version),
// packed via warp ballot. Block = 192 threads = 6 warps = 6 words of one row.
__global__ __launch_bounds__(192) void k_binarize(const float* __restrict__ img){
  int bz = threadIdx.x;              // 0..191 (bit index within row)
  int py = blockIdx.x;               // 0..161 (padded coords)
  int px = blockIdx.y;               // 0..161
  int n  = blockIdx.z;               // 0..1
  int pz = bz - 1;

  unsigned int hard = 0u;
  if (pz >= 0 && pz < 162) {
    uint32_t lin = ((uint32_t)(((n*162 + px)*162) + py))*162u + (uint32_t)pz;
    uint32_t bits = threefry_bits(0u, lin);

    const float minv  = (float)1e-8;
    const float maxv  = (float)(1.0 - 1e-8);    // rounds to 1.0f
    const float range = maxv - minv;            // 1.0f

    float fl = __uint_as_float((bits >> 9) | 0x3f800000u) - 1.0f;
    float u  = fmaxf(minv, __fadd_rn(__fmul_rn(fl, range), minv));
    float noise = __fsub_rn(logf(u), log1pf(-u));

    float p = 0.0f;
    if (px>=1 && px<=160 && py>=1 && py<=160 && pz>=1 && pz<=160)
      p = img[ (((n*160) + (px-1))*160 + (py-1))*160 + (pz-1) ];

    float a = __fadd_rn(p, 1e-8f);
    float b = __fadd_rn(__fsub_rn(1.0f, p), 1e-8f);
    float z = __fadd_rn(logf(__fdiv_rn(a, b)), __fmul_rn(noise, 0.33f));
    float soft = __fdiv_rn(1.0f, __fadd_rn(1.0f, expf(-z)));
    hard = (soft > 0.5f) ? 1u : 0u;
  }
  uint32_t wbits = __ballot_sync(0xffffffffu, hard);
  if ((bz & 31) == 0)
    g_bits[ ((size_t)((n*NR + (px+1))*NR) + (py+1))*ROWW + (bz>>5) ] = wbits;
}

#define ACC(x) { ge2 |= ge1 & (x); ge1 |= (x); }

// Load the 27 z-aligned neighbor bit-vectors for word w of row (bx,by).
#define LOAD_NBRS(B, rowc, w)                                         \
  uint32_t A0[3][3], Am[3][3], Ap[3][3];                              \
  _Pragma("unroll")                                                   \
  for (int dx=0; dx<3; dx++){                                         \
    _Pragma("unroll")                                                 \
    for (int dy=0; dy<3; dy++){                                       \
      const uint32_t* r = (B) + (size_t)((rowc) + (dx-1)*NR + (dy-1))*ROWW; \
      uint32_t c  = r[w];                                             \
      uint32_t pv = (w)      ? r[(w)-1] : 0u;                         \
      uint32_t nx = ((w)<5)  ? r[(w)+1] : 0u;                         \
      A0[dx][dy] = c;                                                 \
      Am[dx][dy] = __funnelshift_l(pv, c, 1);  /* bit z = src z-1 */  \
      Ap[dx][dy] = __funnelshift_r(c, nx, 1);  /* bit z = src z+1 */  \
    }                                                                 \
  }

// Endpoint snapshot: store mask of "26-neighborhood sum >= 2" (i.e. NOT endpoint).
__global__ __launch_bounds__(192) void k_endpoint(){
  int t  = threadIdx.x;
  int w  = t % 6;
  int by = 2 + blockIdx.x*32 + t/6;    // 5 blocks * 32 = 160 interior y
  int bx = 2 + blockIdx.y;             // 160 interior x
  int n  = blockIdx.z;
  const uint32_t* B = g_bits + (size_t)n*NROWW;
  int rowc = bx*NR + by;

  LOAD_NBRS(B, rowc, w);

  uint32_t ge1 = 0u, ge2 = 0u;
  #pragma unroll
  for (int dx=0; dx<3; dx++)
    #pragma unroll
    for (int dy=0; dy<3; dy++){
      if (!(dx==1 && dy==1)) ACC(A0[dx][dy]);
      ACC(Am[dx][dy]); ACC(Ap[dx][dy]);
    }
  g_endb[(size_t)n*NROWW + (size_t)rowc*ROWW + w] = ge2;
}

// One parity-subfield simple-point deletion pass, 32 z-lanes per thread.
__global__ __launch_bounds__(240) void k_subfield(int bx0, int by0, uint32_t pmask){
  int t  = threadIdx.x;
  int w  = t % 6;
  int iy = blockIdx.x*40 + t/6;        // 2 blocks * 40 = 80
  int ix = blockIdx.y;                 // 80
  int n  = blockIdx.z;
  int bx = bx0 + 2*ix, by = by0 + 2*iy;
  uint32_t* V = g_bits + (size_t)n*NROWW;
  int rowc = bx*NR + by;

  LOAD_NBRS(V, rowc, w);

  uint32_t C = A0[1][1];
  uint32_t fxm=A0[0][1], fxp=A0[2][1], fym=A0[1][0], fyp=A0[1][2];
  uint32_t fzm=Am[1][1], fzp=Ap[1][1];

  // face-neighbor count (of ONES) via CSA; n6z = 6 - faceSum
  uint32_t s1 = fxm ^ fxp ^ fym,  c1 = (fxm & fxp) | (fym & (fxm ^ fxp));
  uint32_t s2 = fyp ^ fzm ^ fzp,  c2 = (fyp & fzm) | (fzp & (fyp ^ fzm));
  uint32_t b0 = s1 ^ s2,          hh = s1 & s2;
  uint32_t b1 = c1 ^ c2 ^ hh,     b2 = (c1 & c2) | (hh & (c1 ^ c2));
  uint32_t n6eq5 = b0 & ~b1 & b2;          // n6z == 1
  uint32_t n6le4 = ~(b2 & (b1 | b0));      // n6z >= 2

  // exactly-one over 18-set (faces+edges), then extend by 8 corners -> 26-set
  uint32_t ge1 = fxm | fxp, ge2 = fxm & fxp;
  ACC(fym) ACC(fyp) ACC(fzm) ACC(fzp)
  ACC(A0[0][0]) ACC(A0[0][2]) ACC(A0[2][0]) ACC(A0[2][2])
  ACC(Am[0][1]) ACC(Am[2][1]) ACC(Am[1][0]) ACC(Am[1][2])
  ACC(Ap[0][1]) ACC(Ap[2][1]) ACC(Ap[1][0]) ACC(Ap[1][2])
  uint32_t n18eq1 = ge1 & ~ge2;
  ACC(Am[0][0]) ACC(Am[0][2]) ACC(Am[2][0]) ACC(Am[2][2])
  ACC(Ap[0][0]) ACC(Ap[0][2]) ACC(Ap[2][0]) ACC(Ap[2][2])
  uint32_t n26eq1 = ge1 & ~ge2;

  // b26: corner set with its 6 same-octant face/edge neighbors all clear
  uint32_t anyB = 0u;
#define OCT(AS, sx, sy) {                                                  \
    uint32_t o6 = A0[sx][sy] | AS[sx][1] | A0[sx][1]                       \
                | AS[1][sy] | A0[1][sy] | AS[1][1];                        \
    anyB |= AS[sx][sy] & ~o6; }
  OCT(Am,0,0) OCT(Am,0,2) OCT(Am,2,0) OCT(Am,2,2)
  OCT(Ap,0,0) OCT(Ap,0,2) OCT(Ap,2,0) OCT(Ap,2,2)
#undef OCT

  // a6: face clear with its 4 in-plane edge neighbors all set
  uint32_t anyA =
    (~fxm & A0[0][0] & A0[0][2] & Am[0][1] & Ap[0][1]) |
    (~fxp & A0[2][0] & A0[2][2] & Am[2][1] & Ap[2][1]) |
    (~fym & A0[0][0] & A0[2][0] & Am[1][0] & Ap[1][0]) |
    (~fyp & A0[0][2] & A0[2][2] & Am[1][2] & Ap[1][2]) |
    (~fzm & Am[0][1] & Am[2][1] & Am[1][0] & Am[1][2]) |
    (~fzp & Ap[0][1] & Ap[2][1] & Ap[1][0] & Ap[1][2]);

  uint32_t simple = n6eq5 | n26eq1 | (n18eq1 & ~anyB) | (n6le4 & ~anyA & ~anyB);

  // interior z mask (bz in [2,162)) for this word
  uint32_t wmask = (w==0) ? 0xFFFFFFFCu : ((w==5) ? 0x00000003u : 0xFFFFFFFFu);
  uint32_t endg2 = g_endb[(size_t)n*NROWW + (size_t)rowc*ROWW + w]; // NOT-endpoint
  uint32_t del   = simple & C & endg2 & wmask & pmask;
  V[(size_t)rowc*ROWW + w] = C & ~del;
}

__global__ __launch_bounds__(160) void k_output(float* __restrict__ out){
  int z = threadIdx.x, y = blockIdx.x, x = blockIdx.y, n = blockIdx.z; // 160 each
  int bz = z + 2;
  uint32_t wv = g_bits[ ((size_t)((n*NR + (x+2))*NR) + (y+2))*ROWW + (bz>>5) ];
  out[ ((n*160 + x)*160 + y)*160 + z ] = (float)((wv >> (bz & 31)) & 1u);
}

// ---------------- launch -----------------------------------------------------
extern "C" void kernel_launch(void* const* d_in, const int* in_sizes, int n_in,
                              void* d_out, int out_size){
  (void)in_sizes; (void)n_in; (void)out_size;
  const float* img = (const float*)d_in[0];
  float* out = (float*)d_out;

  k_zero<<<(NWORDS/4 + 255)/256, 256>>>();
  k_binarize<<<dim3(162,162,2), 192>>>(img);

  const int off[8][3] = {{0,0,0},{1,0,0},{0,1,0},{1,1,0},
                         {0,0,1},{1,0,1},{0,1,1},{1,1,1}};
  for (int it=0; it<5; it++){
    k_endpoint<<<dim3(5,160,2), 192>>>();
    for (int s=0; s<8; s++){
      int bx0 = 3 - off[s][0];
      int by0 = 3 - off[s][1];
      int bz0 = 3 - off[s][2];
      uint32_t pmask = (bz0 & 1) ? 0xAAAAAAAAu : 0x55555555u;
      k_subfield<<<dim3(2,80,2), 240>>>(bx0, by0, pmask);
    }
  }
  k_output<<<dim3(160,160,2), 160>>>(out);
}